// round 7
// baseline (speedup 1.0000x reference)
#include <cuda_runtime.h>
#include <cuda_bf16.h>
#include <math.h>

#define SEQ   2048
#define HDIM  512
#define NH    6
#define VOCAB 32000
#define G3    1536          // 3*HDIM
#define GRU_NCTA 64

// ---------------- scratch (device globals; no allocations allowed) -------------
__device__ float g_x   [SEQ*HDIM];                 // embeddings
__device__ float g_q   [NH*SEQ*HDIM];
__device__ float g_k   [NH*SEQ*HDIM];
__device__ float g_v   [NH*SEQ*HDIM];
__device__ float g_sc  [(size_t)NH*SEQ*SEQ];       // attention scores / probs
__device__ float g_cat [SEQ*NH*HDIM];              // concatenated heads (s, h*512+e)
__device__ float g_mha [SEQ*HDIM];
__device__ float g_xln [SEQ*HDIM];                 // post-LN sequence (GRU input)
__device__ float g_gi  [SEQ*G3];                   // x @ W_ih^T + b_ih, all timesteps
__device__ unsigned long long g_ht[2][HDIM];       // tagged hidden: (tag<<32)|f32bits
__device__ float g_logits[VOCAB];
__device__ float g_lse;

// STRONG (morally strong -> single-copy atomic per PTX model) 64-bit ops.
__device__ __forceinline__ unsigned long long ld_acq_u64(const unsigned long long* p){
    unsigned long long v;
    asm volatile("ld.acquire.gpu.global.u64 %0, [%1];" : "=l"(v) : "l"(p) : "memory");
    return v;
}
__device__ __forceinline__ void st_rel_u64(unsigned long long* p, unsigned long long v){
    asm volatile("st.release.gpu.global.u64 [%0], %1;" :: "l"(p), "l"(v) : "memory");
}
__device__ __forceinline__ float tanh_fast(float x){
    float y; asm("tanh.approx.f32 %0, %1;" : "=f"(y) : "f"(x)); return y;
}

// ---------------- packed f32x2 helpers (sm_103a FFMA2 path) --------------------
__device__ __forceinline__ unsigned long long pack2_dup(float x){
    unsigned long long r; unsigned u = __float_as_uint(x);
    asm("mov.b64 %0, {%1, %1};" : "=l"(r) : "r"(u));
    return r;
}
__device__ __forceinline__ void fma2(unsigned long long& d,
                                     unsigned long long a, unsigned long long b){
    asm("fma.rn.f32x2 %0, %1, %2, %0;" : "+l"(d) : "l"(a), "l"(b));
}
__device__ __forceinline__ void unpack2(unsigned long long v, float& lo, float& hi){
    unsigned l, h;
    asm("mov.b64 {%0, %1}, %2;" : "=r"(l), "=r"(h) : "l"(v));
    lo = __uint_as_float(l); hi = __uint_as_float(h);
}

// ---------------- embedding gather ---------------------------------------------
__global__ void embed_kernel(const int* __restrict__ tok,
                             const float* __restrict__ emb)
{
    int s = blockIdx.x;
    long long t = tok[s];
    const float4* src = (const float4*)(emb + t*HDIM);
    float4* dst = (float4*)(g_x + (long long)s*HDIM);
    int i = threadIdx.x;               // 128 threads, 128 float4 = 512 floats
    dst[i] = src[i];
}

// ---------------- fp32 tiled GEMM: C = alpha*(A@B[^T]) + bias[col] -------------
// BM=BN=128, BK=16, 256 threads, 8x8 microtile held as 32 packed f32x2
// accumulators (FFMA2). B-pairs load directly as ulonglong2 from smem (free
// packing); A is duplicated into both lanes via mov.b64 (alu pipe, hidden
// under the fma pipe). Double-buffered smem with register-staged prefetch.
template<bool TRANS_B>
__global__ void __launch_bounds__(256, 2)
gemm128(const float* __restrict__ A, const float* __restrict__ B,
        const float* __restrict__ bias, float* __restrict__ C,
        int M, int N, int K, int lda, int ldb, int ldc,
        long long sA, long long sB, long long sC, long long sBias,
        float alpha)
{
    __shared__ __align__(16) float As[2][16][132];
    __shared__ __align__(16) float Bs[2][16][132];
    A += (long long)blockIdx.z * sA;
    B += (long long)blockIdx.z * sB;
    C += (long long)blockIdx.z * sC;
    const float* bi = bias ? (bias + (long long)blockIdx.z * sBias) : (const float*)0;

    const int bm = blockIdx.y * 128;
    const int bn = blockIdx.x * 128;
    const int tid = threadIdx.x;
    const int tx = tid & 15, ty = tid >> 4;

    unsigned long long acc2[8][4];     // [i][jpair] = (c[i][2jp], c[i][2jp+1])
    #pragma unroll
    for (int i = 0; i < 8; i++)
        #pragma unroll
        for (int jp = 0; jp < 4; jp++) acc2[i][jp] = 0ULL;

    float ra[8], rb[8];

    // prologue: tile 0 -> regs -> buffer 0
    #pragma unroll
    for (int i = 0; i < 8; i++) {
        int idx = tid + i*256;
        int m = idx >> 4, k = idx & 15;
        ra[i] = A[(long long)(bm+m)*lda + k];
        if (TRANS_B) { int n = idx >> 4, kk = idx & 15; rb[i] = B[(long long)(bn+n)*ldb + kk]; }
        else         { int kk = idx >> 7, n = idx & 127; rb[i] = B[(long long)kk*ldb + (bn+n)]; }
    }
    #pragma unroll
    for (int i = 0; i < 8; i++) {
        int idx = tid + i*256;
        int m = idx >> 4, k = idx & 15;
        As[0][k][m] = ra[i];
        if (TRANS_B) { int n = idx >> 4, kk = idx & 15; Bs[0][kk][n] = rb[i]; }
        else         { int kk = idx >> 7, n = idx & 127; Bs[0][kk][n] = rb[i]; }
    }
    __syncthreads();

    int cur = 0;
    for (int k0 = 0; k0 < K; k0 += 16) {
        const bool has_next = (k0 + 16 < K);
        if (has_next) {
            const int kn = k0 + 16;
            #pragma unroll
            for (int i = 0; i < 8; i++) {
                int idx = tid + i*256;
                int m = idx >> 4, k = idx & 15;
                ra[i] = A[(long long)(bm+m)*lda + (kn+k)];
                if (TRANS_B) { int n = idx >> 4, kk = idx & 15; rb[i] = B[(long long)(bn+n)*ldb + (kn+kk)]; }
                else         { int kk = idx >> 7, n = idx & 127; rb[i] = B[(long long)(kn+kk)*ldb + (bn+n)]; }
            }
        }
        #pragma unroll
        for (int kk = 0; kk < 16; kk++) {
            const float* arow = &As[cur][kk][ty*8];
            const float* brow = &Bs[cur][kk][tx*8];
            float4 a0 = *(const float4*)arow;
            float4 a1 = *(const float4*)(arow + 4);
            ulonglong2 b01 = *(const ulonglong2*)brow;        // (b0,b1),(b2,b3)
            ulonglong2 b23 = *(const ulonglong2*)(brow + 4);  // (b4,b5),(b6,b7)
            unsigned long long bp[4] = {b01.x, b01.y, b23.x, b23.y};
            float af[8] = {a0.x,a0.y,a0.z,a0.w,a1.x,a1.y,a1.z,a1.w};
            #pragma unroll
            for (int i = 0; i < 8; i++) {
                unsigned long long aa = pack2_dup(af[i]);
                #pragma unroll
                for (int jp = 0; jp < 4; jp++) fma2(acc2[i][jp], aa, bp[jp]);
            }
        }
        if (has_next) {
            const int nxt = cur ^ 1;
            #pragma unroll
            for (int i = 0; i < 8; i++) {
                int idx = tid + i*256;
                int m = idx >> 4, k = idx & 15;
                As[nxt][k][m] = ra[i];
                if (TRANS_B) { int n = idx >> 4, kk2 = idx & 15; Bs[nxt][kk2][n] = rb[i]; }
                else         { int kk2 = idx >> 7, n = idx & 127; Bs[nxt][kk2][n] = rb[i]; }
            }
            __syncthreads();
            cur = nxt;
        }
    }
    #pragma unroll
    for (int i = 0; i < 8; i++) {
        int row = bm + ty*8 + i;
        float* cp = C + (long long)row*ldc + bn + tx*8;
        float vals[8];
        #pragma unroll
        for (int jp = 0; jp < 4; jp++) unpack2(acc2[i][jp], vals[2*jp], vals[2*jp+1]);
        #pragma unroll
        for (int j = 0; j < 8; j++) {
            float vv = alpha*vals[j];
            if (bi) vv += bi[bn + tx*8 + j];
            cp[j] = vv;
        }
    }
}

// ---------------- row softmax over length-2048 rows ----------------------------
__global__ void softmax2048(float* __restrict__ S)
{
    __shared__ float red[32];
    float* row = S + (long long)blockIdx.x * 2048;
    int tid = threadIdx.x;                         // 256
    float v[8];
    float m = -1e30f;
    #pragma unroll
    for (int i = 0; i < 8; i++) { v[i] = row[tid + i*256]; m = fmaxf(m, v[i]); }
    #pragma unroll
    for (int o = 16; o > 0; o >>= 1) m = fmaxf(m, __shfl_xor_sync(~0u, m, o));
    if ((tid & 31) == 0) red[tid >> 5] = m;
    __syncthreads();
    if (tid == 0) {
        float x = red[0];
        #pragma unroll
        for (int i = 1; i < 8; i++) x = fmaxf(x, red[i]);
        red[0] = x;
    }
    __syncthreads();
    m = red[0];
    __syncthreads();
    float s = 0.0f;
    #pragma unroll
    for (int i = 0; i < 8; i++) { v[i] = __expf(v[i] - m); s += v[i]; }
    #pragma unroll
    for (int o = 16; o > 0; o >>= 1) s += __shfl_xor_sync(~0u, s, o);
    if ((tid & 31) == 0) red[tid >> 5] = s;
    __syncthreads();
    if (tid == 0) {
        float x = 0.0f;
        #pragma unroll
        for (int i = 0; i < 8; i++) x += red[i];
        red[0] = x;
    }
    __syncthreads();
    float inv = 1.0f / red[0];
    #pragma unroll
    for (int i = 0; i < 8; i++) row[tid + i*256] = v[i]*inv;
}

// ---------------- residual + LayerNorm -----------------------------------------
__global__ void resid_ln(const float* __restrict__ gamma, const float* __restrict__ beta)
{
    __shared__ float r1[8], r2[8];
    int s = blockIdx.x, tid = threadIdx.x;         // 256 threads
    const float* xr = g_x   + (long long)s*HDIM;
    const float* mr = g_mha + (long long)s*HDIM;
    float y0 = xr[tid]       + mr[tid];
    float y1 = xr[tid + 256] + mr[tid + 256];
    float sum = y0 + y1, sq = y0*y0 + y1*y1;
    #pragma unroll
    for (int o = 16; o > 0; o >>= 1) {
        sum += __shfl_xor_sync(~0u, sum, o);
        sq  += __shfl_xor_sync(~0u, sq,  o);
    }
    if ((tid & 31) == 0) { r1[tid >> 5] = sum; r2[tid >> 5] = sq; }
    __syncthreads();
    if (tid == 0) {
        float a = 0.0f, b = 0.0f;
        #pragma unroll
        for (int i = 0; i < 8; i++) { a += r1[i]; b += r2[i]; }
        r1[0] = a; r2[0] = b;
    }
    __syncthreads();
    float mu  = r1[0]*(1.0f/512.0f);
    float var = r2[0]*(1.0f/512.0f) - mu*mu;
    float rstd = rsqrtf(var + 1e-5f);
    g_xln[(long long)s*HDIM + tid]       = (y0 - mu)*rstd*gamma[tid]       + beta[tid];
    g_xln[(long long)s*HDIM + 256 + tid] = (y1 - mu)*rstd*gamma[tid + 256] + beta[tid + 256];
}

// ---------------- GRU init: seed h with tag=1, clear stale tags (graph replay!) -
__global__ void gru_init(const float* __restrict__ dec_hid)
{
    int i = threadIdx.x;                           // 512
    g_ht[0][i] = (1ULL << 32) | (unsigned long long)__float_as_uint(dec_hid[i]);
    g_ht[1][i] = 0ULL;                             // stale-tag clear
}

// ---------------- persistent sequential GRU (tag-in-word dataflow sync) --------
// 64 CTAs x 256 threads. Warp w of CTA c owns h-element jj = c*8+w and its three
// gate rows. Strong acquire/release 64-bit tag|value words (single-copy atomic).
__global__ void gru_kernel(const float* __restrict__ W_hh,
                           const float* __restrict__ b_hh)
{
    __shared__ float hs[2][HDIM];
    const int tid = threadIdx.x;
    const int warp = tid >> 5, lane = tid & 31;
    const int jj = blockIdx.x * 8 + warp;          // 0..511

    float wr0[16], wr1[16], wr2[16];
    const float* w0 = W_hh + (long long)(jj        )*HDIM + lane;
    const float* w1 = W_hh + (long long)(jj +  512 )*HDIM + lane;
    const float* w2 = W_hh + (long long)(jj + 1024 )*HDIM + lane;
    #pragma unroll
    for (int i = 0; i < 16; i++) { wr0[i] = w0[32*i]; wr1[i] = w1[32*i]; wr2[i] = w2[32*i]; }
    const float bh0 = b_hh[jj], bh1 = b_hh[jj + 512], bh2 = b_hh[jj + 1024];

    for (int t = 0; t < SEQ; t++) {
        // prefetch gi for this step (uniform address across the warp -> broadcast)
        float gr = __ldcg(&g_gi[(long long)t*G3 + jj]);
        float gz = __ldcg(&g_gi[(long long)t*G3 + jj + 512]);
        float gn = __ldcg(&g_gi[(long long)t*G3 + jj + 1024]);

        // poll: both loads in flight before first check
        const unsigned long long* hb = g_ht[t & 1];
        const unsigned expect = (unsigned)(t + 1);
        unsigned long long v0 = ld_acq_u64(&hb[tid]);
        unsigned long long v1 = ld_acq_u64(&hb[tid + 256]);
        while ((unsigned)(v0 >> 32) != expect) v0 = ld_acq_u64(&hb[tid]);
        while ((unsigned)(v1 >> 32) != expect) v1 = ld_acq_u64(&hb[tid + 256]);

        float* hcur = hs[t & 1];
        hcur[tid]       = __uint_as_float((unsigned)v0);
        hcur[tid + 256] = __uint_as_float((unsigned)v1);
        __syncthreads();

        float hprev = hcur[jj];
        float a0 = 0.0f, a1 = 0.0f, a2 = 0.0f;
        #pragma unroll
        for (int i = 0; i < 16; i++) {
            float h = hcur[lane + 32*i];
            a0 += h*wr0[i];
            a1 += h*wr1[i];
            a2 += h*wr2[i];
        }
        #pragma unroll
        for (int o = 16; o > 0; o >>= 1) {
            a0 += __shfl_xor_sync(~0u, a0, o);
            a1 += __shfl_xor_sync(~0u, a1, o);
            a2 += __shfl_xor_sync(~0u, a2, o);
        }

        if (lane == 0) {
            float r = 0.5f + 0.5f*tanh_fast(0.5f*(gr + a0 + bh0));
            float z = 0.5f + 0.5f*tanh_fast(0.5f*(gz + a1 + bh1));
            float n = tanh_fast(gn + r*(a2 + bh2));
            float hnew = fmaf(z, hprev - n, n);    // (1-z)*n + z*h
            unsigned long long w = ((unsigned long long)(unsigned)(t + 2) << 32)
                                 | (unsigned long long)__float_as_uint(hnew);
            st_rel_u64(&g_ht[(t + 1) & 1][jj], w);
        }
        // no trailing barrier: hs is double-buffered; overwrite of hs[b] occurs at
        // step t+2 whose poll is gated on tags that prove every warp published t+1,
        // and each publish data-depends on that warp's completed reads of hs[b].
    }
}

// ---------------- final projection: logits = h @ W_out + b_out -----------------
// final h (t=2048, tag 2049) lives in g_ht[0] low words
__global__ void logits_kernel(const float* __restrict__ W_out,
                              const float* __restrict__ b_out)
{
    __shared__ float hsm[HDIM];
    for (int i = threadIdx.x; i < HDIM; i += 256)
        hsm[i] = __uint_as_float((unsigned)g_ht[0][i]);
    __syncthreads();
    int v = blockIdx.x*256 + threadIdx.x;
    if (v >= VOCAB) return;
    float acc = b_out[v];
    #pragma unroll 4
    for (int d = 0; d < HDIM; d++) acc += hsm[d]*W_out[(long long)d*VOCAB + v];
    g_logits[v] = acc;
}

__global__ void lse_kernel()
{
    __shared__ float red[32];
    int tid = threadIdx.x;                         // 1024
    float m = -1e30f;
    for (int i = tid; i < VOCAB; i += 1024) m = fmaxf(m, g_logits[i]);
    #pragma unroll
    for (int o = 16; o > 0; o >>= 1) m = fmaxf(m, __shfl_xor_sync(~0u, m, o));
    if ((tid & 31) == 0) red[tid >> 5] = m;
    __syncthreads();
    if (tid == 0) {
        float x = red[0];
        #pragma unroll
        for (int i = 1; i < 32; i++) x = fmaxf(x, red[i]);
        red[0] = x;
    }
    __syncthreads();
    m = red[0];
    __syncthreads();
    float s = 0.0f;
    for (int i = tid; i < VOCAB; i += 1024) s += expf(g_logits[i] - m);
    #pragma unroll
    for (int o = 16; o > 0; o >>= 1) s += __shfl_xor_sync(~0u, s, o);
    if ((tid & 31) == 0) red[tid >> 5] = s;
    __syncthreads();
    if (tid == 0) {
        float x = 0.0f;
        #pragma unroll
        for (int i = 0; i < 32; i++) x += red[i];
        g_lse = m + logf(x);
    }
}

__global__ void out_kernel(float* __restrict__ out)
{
    int i = blockIdx.x*256 + threadIdx.x;
    if (i < VOCAB)            out[i] = g_logits[i] - g_lse;
    else if (i < VOCAB+HDIM)  out[i] = __uint_as_float((unsigned)g_ht[0][i - VOCAB]);
}

// ================================ host side =====================================
extern "C" void kernel_launch(void* const* d_in, const int* in_sizes, int n_in,
                              void* d_out, int out_size)
{
    const int*   tok     = (const int*)  d_in[0];
    const float* dec_hid = (const float*)d_in[1];
    const float* emb     = (const float*)d_in[2];
    const float* Wq      = (const float*)d_in[3];
    const float* bq      = (const float*)d_in[4];
    const float* Wk      = (const float*)d_in[5];
    const float* bk      = (const float*)d_in[6];
    const float* Wv      = (const float*)d_in[7];
    const float* bv      = (const float*)d_in[8];
    const float* Wo      = (const float*)d_in[9];
    const float* bo      = (const float*)d_in[10];
    const float* gamma   = (const float*)d_in[11];
    const float* beta    = (const float*)d_in[12];
    const float* W_ih    = (const float*)d_in[13];
    const float* W_hh    = (const float*)d_in[14];
    const float* b_ih    = (const float*)d_in[15];
    const float* b_hh    = (const float*)d_in[16];
    const float* W_out   = (const float*)d_in[17];
    const float* b_out   = (const float*)d_in[18];
    float* out = (float*)d_out;

    float *px, *pq, *pk, *pV, *psc, *pcat, *pmha, *pxln, *pgi;
    cudaGetSymbolAddress((void**)&px,   g_x);
    cudaGetSymbolAddress((void**)&pq,   g_q);
    cudaGetSymbolAddress((void**)&pk,   g_k);
    cudaGetSymbolAddress((void**)&pV,   g_v);
    cudaGetSymbolAddress((void**)&psc,  g_sc);
    cudaGetSymbolAddress((void**)&pcat, g_cat);
    cudaGetSymbolAddress((void**)&pmha, g_mha);
    cudaGetSymbolAddress((void**)&pxln, g_xln);
    cudaGetSymbolAddress((void**)&pgi,  g_gi);

    // 1) embedding gather
    embed_kernel<<<SEQ, 128>>>(tok, emb);

    // 2) Q/K/V projections: (2048x512)@(512x512) per head, batched over heads
    gemm128<false><<<dim3(4,16,NH), 256>>>(px, Wq, bq, pq, SEQ, HDIM, HDIM,
        HDIM, HDIM, HDIM, 0LL, (long long)HDIM*HDIM, (long long)SEQ*HDIM, HDIM, 1.0f);
    gemm128<false><<<dim3(4,16,NH), 256>>>(px, Wk, bk, pk, SEQ, HDIM, HDIM,
        HDIM, HDIM, HDIM, 0LL, (long long)HDIM*HDIM, (long long)SEQ*HDIM, HDIM, 1.0f);
    gemm128<false><<<dim3(4,16,NH), 256>>>(px, Wv, bv, pV, SEQ, HDIM, HDIM,
        HDIM, HDIM, HDIM, 0LL, (long long)HDIM*HDIM, (long long)SEQ*HDIM, HDIM, 1.0f);

    // 3) scores = Q @ K^T / sqrt(H)
    gemm128<true><<<dim3(16,16,NH), 256>>>(pq, pk, (const float*)0, psc,
        SEQ, SEQ, HDIM, HDIM, HDIM, SEQ,
        (long long)SEQ*HDIM, (long long)SEQ*HDIM, (long long)SEQ*SEQ, 0LL,
        0.04419417382415922f);

    // 4) softmax over last dim
    softmax2048<<<NH*SEQ, 256>>>(psc);

    // 5) heads = P @ V, written directly into concat layout (col offset h*512)
    gemm128<false><<<dim3(4,16,NH), 256>>>(psc, pV, (const float*)0, pcat,
        SEQ, HDIM, SEQ, SEQ, HDIM, NH*HDIM,
        (long long)SEQ*SEQ, (long long)SEQ*HDIM, (long long)HDIM, 0LL, 1.0f);

    // 6) mha = cat @ Wo + bo
    gemm128<false><<<dim3(4,16,1), 256>>>(pcat, Wo, bo, pmha,
        SEQ, HDIM, NH*HDIM, NH*HDIM, HDIM, HDIM, 0LL, 0LL, 0LL, 0LL, 1.0f);

    // 7) residual + layernorm
    resid_ln<<<SEQ, 256>>>(gamma, beta);

    // 8) gi = xln @ W_ih^T + b_ih (all timesteps, parallel)
    gemm128<true><<<dim3(12,16,1), 256>>>(pxln, W_ih, b_ih, pgi,
        SEQ, G3, HDIM, HDIM, HDIM, G3, 0LL, 0LL, 0LL, 0LL, 1.0f);

    // 9) sequential GRU (persistent, register-resident W_hh, tag-word dataflow)
    gru_init<<<1, 512>>>(dec_hid);
    gru_kernel<<<GRU_NCTA, 256>>>(W_hh, b_hh);

    // 10) logits + log_softmax + outputs
    logits_kernel<<<(VOCAB+255)/256, 256>>>(W_out, b_out);
    lse_kernel<<<1, 1024>>>();
    out_kernel<<<(VOCAB+HDIM+255)/256, 256>>>(out);
}